// round 13
// baseline (speedup 1.0000x reference)
#include <cuda_runtime.h>
#include <math.h>
#include <stdint.h>

#define BN   4
#define VN   256
#define C1N  64
#define C2N  32
#define H0N  128
#define H2N  256

// ---------------- scratch ----------------
__device__ float g_A [BN*VN*H0N];
__device__ float g_Bv[BN*VN*H0N];
__device__ float g_x1[BN*VN*H0N];
__device__ float g_x2[BN*VN*H0N];
__device__ float g_P [BN*VN*H2N];
__device__ float g_Q [BN*VN*H2N];
__device__ __align__(16) uint32_t g_Ebf[BN*VN*VN*16];   // e packed bf16x2: [bi*256+j][16]
__device__ __align__(16) uint32_t g_WP [2*10240];       // per layer: W1eT[128][16] | W2T[128][64]

__device__ __forceinline__ uint32_t pack_bf2(float lo, float hi) {
    uint32_t r;
    asm("cvt.rn.bf16x2.f32 %0, %1, %2;" : "=r"(r) : "f"(hi), "f"(lo));
    return r;
}
__device__ __forceinline__ void mma_bf16(float* c, const uint32_t* a, const uint32_t* b) {
    asm volatile("mma.sync.aligned.m16n8k16.row.col.f32.bf16.bf16.f32 "
        "{%0,%1,%2,%3}, {%4,%5,%6,%7}, {%8,%9}, {%0,%1,%2,%3};"
        : "+f"(c[0]), "+f"(c[1]), "+f"(c[2]), "+f"(c[3])
        : "r"(a[0]), "r"(a[1]), "r"(a[2]), "r"(a[3]), "r"(b[0]), "r"(b[1]));
}
#define CP_ASYNC16(dst, src) \
    asm volatile("cp.async.ca.shared.global [%0], [%1], 16;" :: "r"(dst), "l"(src))
#define CP_COMMIT() asm volatile("cp.async.commit_group;" ::: "memory")
#define CP_WAIT(n)  asm volatile("cp.async.wait_group %0;" :: "n"(n) : "memory")

// SMEM layout in 32-bit words (bf16x2 words; strides 20/68 keep frag LDS conflict-free)
#define OFF_W1E 0                       // [128 n][16 kw] stride 20 -> 2560
#define OFF_W2T (OFF_W1E + 128*20)      // [128 n][64 kw] stride 68 -> 8704
#define OFF_E   (OFF_W2T + 128*68)      // 2 bufs x [128 j][16 kw] stride 20
#define OFF_H1  (OFF_E   + 2*128*20)    // [128 j][64 kw] stride 68
#define OFF_A   (OFF_H1  + 128*68)      // f32 x128
#define OFF_B2  (OFF_A + 128)
#define OFF_ADJ (OFF_B2 + 128)
#define OFF_RED (OFF_ADJ + 256)
#define SMEM_WORDS (OFF_RED + 4*132)
#define SMEM_BYTES (SMEM_WORDS * 4)     // ~104.5 KB -> 2 CTAs/SM

// ---------------------------------------------------------------------------
// pack e -> bf16x2 rows. grid 1024 x 256 thr; one j-row (32 f32 -> 16 words) each.
__global__ void e_pack_kernel(const float* __restrict__ e, uint32_t* __restrict__ out)
{
    const int row = blockIdx.x * 256 + threadIdx.x;   // 0 .. 262143
    const float4* src = (const float4*)(e + (size_t)row * 32);
    uint4* dst = (uint4*)(out + (size_t)row * 16);
    uint4 o;
#pragma unroll
    for (int q = 0; q < 4; q++) {
        float4 a = src[q * 2], b = src[q * 2 + 1];
        o.x = pack_bf2(a.x, a.y); o.y = pack_bf2(a.z, a.w);
        o.z = pack_bf2(b.x, b.y); o.w = pack_bf2(b.z, b.w);
        dst[q] = o;
    }
}
// pack one layer's weights: W1eT [n][16kw], then W2T [n][64kw]. grid 40 x 256.
__global__ void w_pack_kernel(const float* __restrict__ W1e,
                              const float* __restrict__ W2,
                              uint32_t* __restrict__ out)
{
    const int idx = blockIdx.x * 256 + threadIdx.x;   // 0..10239
    if (idx < 2048) {
        int n = idx >> 4, kw = idx & 15;
        out[idx] = pack_bf2(W1e[(2*kw) * 128 + n], W1e[(2*kw + 1) * 128 + n]);
    } else {
        int i2 = idx - 2048;
        int n = i2 >> 6, kw = i2 & 63;
        out[idx] = pack_bf2(W2[(2*kw) * 128 + n], W2[(2*kw + 1) * 128 + n]);
    }
}

// ---------------------------------------------------------------------------
// prep_node: 256 CTAs x 4 nodes, 128 threads.
template<int C>
__global__ void prep_node3(const float* __restrict__ x,
                           const float* __restrict__ W1,
                           const float* __restrict__ b1,
                           float* __restrict__ A,
                           float* __restrict__ Bout)
{
    __shared__ float sx[4 * C];
    const int ni0 = blockIdx.x * 4;
    const int h   = threadIdx.x;     // 128
    for (int idx = h; idx < 4 * C; idx += 128)
        sx[idx] = x[(size_t)ni0 * C + idx];
    __syncthreads();
    float accA[4] = {0.f, 0.f, 0.f, 0.f};
    float accB[4] = {0.f, 0.f, 0.f, 0.f};
#pragma unroll 4
    for (int c = 0; c < C; c++) {
        float wa = W1[c * 128 + h];
        float wb = W1[(C + c) * 128 + h];
        float d  = wa - wb;
#pragma unroll
        for (int r = 0; r < 4; r++) {
            float xa = sx[r * C + c];
            accA[r] += xa * d;
            accB[r] += xa * wb;
        }
    }
    const float bb = b1[h];
#pragma unroll
    for (int r = 0; r < 4; r++) {
        A   [(size_t)(ni0 + r) * 128 + h] = accA[r] + bb;
        Bout[(size_t)(ni0 + r) * 128 + h] = accB[r];
    }
}

// ---------------------------------------------------------------------------
// Fused edgeconv, bf16 mma + cp.async staging. One CTA per (b,i), 256 threads,
// 8 warps = 4 M-groups x 2 N-groups. 2 chunks of 128 j-rows, E double-buffered.
__global__ __launch_bounds__(256, 2)
void fused_ec_bf16(const int*      __restrict__ adj,
                   const uint32_t* __restrict__ Ebf,   // packed e
                   const float*    __restrict__ A,
                   const float*    __restrict__ Bnode,
                   const uint32_t* __restrict__ Wp,    // packed weights (this layer)
                   const float*    __restrict__ b2,
                   float* __restrict__ xout)
{
    extern __shared__ float smem[];
    uint32_t* s32 = (uint32_t*)smem;
    const uint32_t sb = (uint32_t)__cvta_generic_to_shared(smem);
    const int tid  = threadIdx.x;
    const int lane = tid & 31;
    const int wid  = tid >> 5;
    const int gid  = lane >> 2;      // 0..7
    const int tig  = lane & 3;       // 0..3
    const int WM   = wid & 3;        // rows WM*32 .. +31
    const int WN   = wid >> 2;       // cols WN*64 .. +63
    const int m0   = WM * 32;
    const int n0   = WN * 64;
    const int bi   = blockIdx.x;     // b*256 + i
    const int b    = bi >> 8;

    // ---- async stage: W1E (2 x 16B per thread), W2T (8 x), E0 (2 x) ----
    {
        // W1E: 512 chunks of 16B: chunk c -> row n=c>>2, seg=c&3
        int c0 = tid * 2;
#pragma unroll
        for (int q = 0; q < 2; q++) {
            int c = c0 + q, n = c >> 2, seg = c & 3;
            CP_ASYNC16(sb + (uint32_t)(OFF_W1E + n * 20 + seg * 4) * 4,
                       (const void*)(Wp + n * 16 + seg * 4));
        }
        // W2T: 2048 chunks: c -> n=c>>4, seg=c&15
        int c1 = tid * 8;
#pragma unroll
        for (int q = 0; q < 8; q++) {
            int c = c1 + q, n = c >> 4, seg = c & 15;
            CP_ASYNC16(sb + (uint32_t)(OFF_W2T + n * 68 + seg * 4) * 4,
                       (const void*)(Wp + 2048 + n * 64 + seg * 4));
        }
        // E chunk0: 512 chunks: c -> row=c>>2, seg=c&3
#pragma unroll
        for (int q = 0; q < 2; q++) {
            int c = c0 + q, row = c >> 2, seg = c & 3;
            CP_ASYNC16(sb + (uint32_t)(OFF_E + row * 20 + seg * 4) * 4,
                       (const void*)(Ebf + ((size_t)bi * 256 + row) * 16 + seg * 4));
        }
    }
    CP_COMMIT();   // group 0: W + E0
    // E chunk1 -> buffer 1
    {
        int c0 = tid * 2;
#pragma unroll
        for (int q = 0; q < 2; q++) {
            int c = c0 + q, row = c >> 2, seg = c & 3;
            CP_ASYNC16(sb + (uint32_t)(OFF_E + 2560 + row * 20 + seg * 4) * 4,
                       (const void*)(Ebf + ((size_t)bi * 256 + 128 + row) * 16 + seg * 4));
        }
    }
    CP_COMMIT();   // group 1: E1

    // regular loads (overlap with cp.async)
    if (tid < 128) {
        smem[OFF_A  + tid] = A[(size_t)bi * 128 + tid];
        smem[OFF_B2 + tid] = b2[tid];
    }
    ((int*)(smem + OFF_ADJ))[tid] = adj[(size_t)bi * 256 + tid];

    CP_WAIT(1);            // W + E0 complete
    __syncthreads();

    float pmax = 0.0f;

    for (int chunk = 0; chunk < 2; chunk++) {
        const int j0 = chunk << 7;
        const int eb = OFF_E + chunk * 2560;

        float acc[2][8][4];
#pragma unroll
        for (int mt = 0; mt < 2; mt++)
#pragma unroll
            for (int nt = 0; nt < 8; nt++)
#pragma unroll
                for (int q = 0; q < 4; q++) acc[mt][nt][q] = 0.f;

        // ---- GEMM1: D1 = E @ W1e  (K=32 -> 2 bf16 k-steps) ----
#pragma unroll
        for (int ks = 0; ks < 2; ks++) {
            const int k0 = ks * 8;
            uint32_t af[2][4];
#pragma unroll
            for (int mt = 0; mt < 2; mt++) {
                const uint32_t* p = s32 + eb + (m0 + mt*16 + gid) * 20 + k0 + tig;
                af[mt][0] = p[0];
                af[mt][1] = p[8 * 20];
                af[mt][2] = p[4];
                af[mt][3] = p[8 * 20 + 4];
            }
#pragma unroll
            for (int nt = 0; nt < 8; nt++) {
                const uint32_t* q = s32 + OFF_W1E + (n0 + nt*8 + gid) * 20 + k0 + tig;
                uint32_t bf[2] = { q[0], q[4] };
                mma_bf16(acc[0][nt], af[0], bf);
                mma_bf16(acc[1][nt], af[1], bf);
            }
        }

        // ---- epilogue 1: H1 = relu(D1 + A_i[n] + Bnode[j,n]) -> bf16x2 ----
        {
            const float* sA_ = smem + OFF_A;
#pragma unroll
            for (int mt = 0; mt < 2; mt++) {
                const int r_lo = m0 + mt*16 + gid;
                const int r_hi = r_lo + 8;
                const float2* blo = (const float2*)(Bnode + ((size_t)(b*256 + j0 + r_lo)) * 128);
                const float2* bhi = (const float2*)(Bnode + ((size_t)(b*256 + j0 + r_hi)) * 128);
#pragma unroll
                for (int nt = 0; nt < 8; nt++) {
                    const int ncol = n0 + nt*8 + 2*tig;      // even
                    float2 bl = blo[ncol >> 1];
                    float2 bh = bhi[ncol >> 1];
                    float a0v = sA_[ncol], a1v = sA_[ncol + 1];
                    float h00 = fmaxf(acc[mt][nt][0] + a0v + bl.x, 0.f);
                    float h01 = fmaxf(acc[mt][nt][1] + a1v + bl.y, 0.f);
                    float h10 = fmaxf(acc[mt][nt][2] + a0v + bh.x, 0.f);
                    float h11 = fmaxf(acc[mt][nt][3] + a1v + bh.y, 0.f);
                    s32[OFF_H1 + r_lo * 68 + (ncol >> 1)] = pack_bf2(h00, h01);
                    s32[OFF_H1 + r_hi * 68 + (ncol >> 1)] = pack_bf2(h10, h11);
                }
            }
        }
        __syncthreads();

#pragma unroll
        for (int mt = 0; mt < 2; mt++)
#pragma unroll
            for (int nt = 0; nt < 8; nt++)
#pragma unroll
                for (int q = 0; q < 4; q++) acc[mt][nt][q] = 0.f;

        // ---- GEMM2: D2 = H1 @ W2  (K=128 -> 8 bf16 k-steps) ----
#pragma unroll 2
        for (int ks = 0; ks < 8; ks++) {
            const int k0 = ks * 8;
            uint32_t af[2][4];
#pragma unroll
            for (int mt = 0; mt < 2; mt++) {
                const uint32_t* p = s32 + OFF_H1 + (m0 + mt*16 + gid) * 68 + k0 + tig;
                af[mt][0] = p[0];
                af[mt][1] = p[8 * 68];
                af[mt][2] = p[4];
                af[mt][3] = p[8 * 68 + 4];
            }
#pragma unroll
            for (int nt = 0; nt < 8; nt++) {
                const uint32_t* q = s32 + OFF_W2T + (n0 + nt*8 + gid) * 68 + k0 + tig;
                uint32_t bf[2] = { q[0], q[4] };
                mma_bf16(acc[0][nt], af[0], bf);
                mma_bf16(acc[1][nt], af[1], bf);
            }
        }

        // ---- epilogue 2: bias+relu+mask, warp row-max -> red[WM][col] ----
        {
            const int* sAdj = (const int*)(smem + OFF_ADJ);
            const float* sb2_ = smem + OFF_B2;
            float* red = smem + OFF_RED;
            const bool kLo  = sAdj[j0 + m0 + gid]      > 0;
            const bool kHi  = sAdj[j0 + m0 + 8 + gid]  > 0;
            const bool kLo1 = sAdj[j0 + m0 + 16 + gid] > 0;
            const bool kHi1 = sAdj[j0 + m0 + 24 + gid] > 0;
#pragma unroll
            for (int nt = 0; nt < 8; nt++) {
                const int ncol = n0 + nt*8 + 2*tig;
                const float bb0 = sb2_[ncol], bb1 = sb2_[ncol + 1];
                float vA = 0.f, vB = 0.f;
                if (kLo)  { vA = fmaxf(vA, acc[0][nt][0] + bb0);
                            vB = fmaxf(vB, acc[0][nt][1] + bb1); }
                if (kHi)  { vA = fmaxf(vA, acc[0][nt][2] + bb0);
                            vB = fmaxf(vB, acc[0][nt][3] + bb1); }
                if (kLo1) { vA = fmaxf(vA, acc[1][nt][0] + bb0);
                            vB = fmaxf(vB, acc[1][nt][1] + bb1); }
                if (kHi1) { vA = fmaxf(vA, acc[1][nt][2] + bb0);
                            vB = fmaxf(vB, acc[1][nt][3] + bb1); }
#pragma unroll
                for (int msk = 4; msk <= 16; msk <<= 1) {
                    vA = fmaxf(vA, __shfl_xor_sync(0xffffffffu, vA, msk));
                    vB = fmaxf(vB, __shfl_xor_sync(0xffffffffu, vB, msk));
                }
                if (gid == 0) {
                    red[WM * 132 + ncol]     = vA;
                    red[WM * 132 + ncol + 1] = vB;
                }
            }
        }
        __syncthreads();
        if (tid < 128) {
            float v = fmaxf(fmaxf(smem[OFF_RED + tid],          smem[OFF_RED + 132 + tid]),
                            fmaxf(smem[OFF_RED + 2*132 + tid],  smem[OFF_RED + 3*132 + tid]));
            pmax = fmaxf(pmax, v);
        }
        if (chunk == 0) {
            CP_WAIT(0);        // E1 ready
            __syncthreads();   // also fences red reads before next chunk's writes
        }
    }

    if (tid < 128) xout[(size_t)bi * 128 + tid] = pmax;
}

// ---------------------------------------------------------------------------
// pair prep: 256 CTAs x 4 rows, 256 threads.
__global__ void pair_prep3(const float* __restrict__ x,     // (B*V,128)
                           const float* __restrict__ W3,    // (256,256)
                           float* __restrict__ P,
                           float* __restrict__ Q)
{
    __shared__ float sx[4 * 128];
    const int ni0 = blockIdx.x * 4;
    const int h   = threadIdx.x;     // 256
    for (int idx = h; idx < 4 * 128; idx += 256)
        sx[idx] = x[(size_t)ni0 * 128 + idx];
    __syncthreads();
    float accP[4] = {0.f, 0.f, 0.f, 0.f};
    float accQ[4] = {0.f, 0.f, 0.f, 0.f};
#pragma unroll 4
    for (int c = 0; c < 128; c++) {
        float wp = W3[c * 256 + h];
        float wq = W3[(128 + c) * 256 + h];
#pragma unroll
        for (int r = 0; r < 4; r++) {
            float xa = sx[r * 128 + c];
            accP[r] += xa * wp;
            accQ[r] += xa * wq;
        }
    }
#pragma unroll
    for (int r = 0; r < 4; r++) {
        P[(size_t)(ni0 + r) * 256 + h] = accP[r];
        Q[(size_t)(ni0 + r) * 256 + h] = accQ[r];
    }
}

// ---------------------------------------------------------------------------
// pair final: 256 CTAs; each handles (b, 4 i-rows) x all 256 j.
__global__ void pair_final3(const float* __restrict__ P,
                            const float* __restrict__ Q,
                            const float* __restrict__ b3,
                            const float* __restrict__ oW,
                            const float* __restrict__ ob,
                            float* __restrict__ out)        // (B,V,V)
{
    __shared__ float sQ[4 * 256];
    __shared__ float sW[256];
    const int blk = blockIdx.x;
    const int b   = blk >> 6;
    const int i0  = (blk & 63) * 4;
    const int tid = threadIdx.x;     // 256
    const int w   = tid >> 5, lane = tid & 31;
    sW[tid] = oW[tid];
    {
        float bb = b3[tid];
#pragma unroll
        for (int r = 0; r < 4; r++)
            sQ[r * 256 + tid] = Q[(size_t)(b * 256 + i0 + r) * 256 + tid] + bb;
    }
    __syncthreads();
    const float outb = ob[0];

    for (int j = w; j < 256; j += 8) {
        const float* pr = P + (size_t)(b * 256 + j) * 256;
        float s0 = 0.f, s1 = 0.f, s2 = 0.f, s3 = 0.f;
#pragma unroll
        for (int q = 0; q < 8; q++) {
            int hh = q * 32 + lane;
            float pv = pr[hh];
            float wv = sW[hh];
            s0 += fmaxf(pv + sQ[          hh], 0.f) * wv;
            s1 += fmaxf(pv + sQ[256     + hh], 0.f) * wv;
            s2 += fmaxf(pv + sQ[2 * 256 + hh], 0.f) * wv;
            s3 += fmaxf(pv + sQ[3 * 256 + hh], 0.f) * wv;
        }
#pragma unroll
        for (int off = 16; off > 0; off >>= 1) {
            s0 += __shfl_xor_sync(0xffffffffu, s0, off);
            s1 += __shfl_xor_sync(0xffffffffu, s1, off);
            s2 += __shfl_xor_sync(0xffffffffu, s2, off);
            s3 += __shfl_xor_sync(0xffffffffu, s3, off);
        }
        if (lane == 0) {
            out[(size_t)(b * 256 + i0 + 0) * 256 + j] = 1.0f / (1.0f + expf(-(s0 + outb)));
            out[(size_t)(b * 256 + i0 + 1) * 256 + j] = 1.0f / (1.0f + expf(-(s1 + outb)));
            out[(size_t)(b * 256 + i0 + 2) * 256 + j] = 1.0f / (1.0f + expf(-(s2 + outb)));
            out[(size_t)(b * 256 + i0 + 3) * 256 + j] = 1.0f / (1.0f + expf(-(s3 + outb)));
        }
    }
}

// ---------------------------------------------------------------------------
extern "C" void kernel_launch(void* const* d_in, const int* in_sizes, int n_in,
                              void* d_out, int out_size)
{
    const int*   adj   = (const int*)  d_in[0];
    const float* x0    = (const float*)d_in[1];
    const float* e     = (const float*)d_in[2];
    const float* ec1W1 = (const float*)d_in[3];
    const float* ec1b1 = (const float*)d_in[4];
    const float* ec1W2 = (const float*)d_in[5];
    const float* ec1b2 = (const float*)d_in[6];
    const float* ec2W1 = (const float*)d_in[7];
    const float* ec2b1 = (const float*)d_in[8];
    const float* ec2W2 = (const float*)d_in[9];
    const float* ec2b2 = (const float*)d_in[10];
    const float* h3W   = (const float*)d_in[11];
    const float* h3b   = (const float*)d_in[12];
    const float* oW    = (const float*)d_in[13];
    const float* ob    = (const float*)d_in[14];
    float* out = (float*)d_out;

    float *gA, *gB, *gx1, *gx2, *gP, *gQ;
    uint32_t *gEbf, *gWP;
    cudaGetSymbolAddress((void**)&gA,   g_A);
    cudaGetSymbolAddress((void**)&gB,   g_Bv);
    cudaGetSymbolAddress((void**)&gx1,  g_x1);
    cudaGetSymbolAddress((void**)&gx2,  g_x2);
    cudaGetSymbolAddress((void**)&gP,   g_P);
    cudaGetSymbolAddress((void**)&gQ,   g_Q);
    cudaGetSymbolAddress((void**)&gEbf, g_Ebf);
    cudaGetSymbolAddress((void**)&gWP,  g_WP);

    const int nBI = BN * VN;  // 1024
    cudaFuncSetAttribute(fused_ec_bf16,
                         cudaFuncAttributeMaxDynamicSharedMemorySize, SMEM_BYTES);

    // one-time packs
    e_pack_kernel<<<1024, 256>>>(e, gEbf);
    w_pack_kernel<<<40, 256>>>(ec1W1 + 2 * C1N * H0N, ec1W2, gWP);
    w_pack_kernel<<<40, 256>>>(ec2W1 + 2 * H0N * H0N, ec2W2, gWP + 10240);

    // EdgeConvE #1
    prep_node3<C1N><<<256, 128>>>(x0, ec1W1, ec1b1, gA, gB);
    fused_ec_bf16<<<nBI, 256, SMEM_BYTES>>>(adj, gEbf, gA, gB, gWP, ec1b2, gx1);
    // EdgeConvE #2
    prep_node3<H0N><<<256, 128>>>(gx1, ec2W1, ec2b1, gA, gB);
    fused_ec_bf16<<<nBI, 256, SMEM_BYTES>>>(adj, gEbf, gA, gB, gWP + 10240, ec2b2, gx2);
    // pair scoring
    pair_prep3 <<<256, 256>>>(gx2, h3W, gP, gQ);
    pair_final3<<<256, 256>>>(gP, gQ, h3b, oW, ob, out);
}

// round 14
// speedup vs baseline: 1.1309x; 1.1309x over previous
#include <cuda_runtime.h>
#include <math.h>
#include <stdint.h>

#define BN   4
#define VN   256
#define C1N  64
#define C2N  32
#define H0N  128
#define H2N  256

// ---------------- scratch ----------------
__device__ float g_A [BN*VN*H0N];
__device__ float g_Bv[BN*VN*H0N];
__device__ float g_x1[BN*VN*H0N];
__device__ float g_x2[BN*VN*H0N];
__device__ float g_P [BN*VN*H2N];
__device__ float g_Q [BN*VN*H2N];

// pack two f32 -> bf16x2 (lo = first arg, hi = second)
__device__ __forceinline__ uint32_t pack_bf2(float lo, float hi) {
    uint32_t r;
    asm("cvt.rn.bf16x2.f32 %0, %1, %2;" : "=r"(r) : "f"(hi), "f"(lo));
    return r;
}
__device__ __forceinline__ void mma_bf16(float* c, const uint32_t* a, const uint32_t* b) {
    asm volatile("mma.sync.aligned.m16n8k16.row.col.f32.bf16.bf16.f32 "
        "{%0,%1,%2,%3}, {%4,%5,%6,%7}, {%8,%9}, {%0,%1,%2,%3};"
        : "+f"(c[0]), "+f"(c[1]), "+f"(c[2]), "+f"(c[3])
        : "r"(a[0]), "r"(a[1]), "r"(a[2]), "r"(a[3]), "r"(b[0]), "r"(b[1]));
}
__device__ __forceinline__ void ldsm_x4(uint32_t* r, uint32_t addr) {
    asm volatile("ldmatrix.sync.aligned.m8n8.x4.shared.b16 {%0,%1,%2,%3}, [%4];"
        : "=r"(r[0]), "=r"(r[1]), "=r"(r[2]), "=r"(r[3]) : "r"(addr));
}

// SMEM layout in 32-bit words (bf16x2 words; strides 20/68: ldmatrix rows land
// in distinct bank quads: 20r mod 32 and 68r mod 32 both cycle through 8
// distinct values for r=0..7 -> conflict-free LDSM)
#define OFF_W1E 0                      // [128 n][16 kw] stride 20
#define OFF_W2T (OFF_W1E + 128*20)     // [128 n][64 kw] stride 68
#define OFF_E   (OFF_W2T + 128*68)     // [128 j][16 kw] stride 20
#define OFF_H1  (OFF_E   + 128*20)     // [128 j][64 kw] stride 68
#define OFF_A   (OFF_H1  + 128*68)     // f32 x128
#define OFF_B2  (OFF_A + 128)
#define OFF_ADJ (OFF_B2 + 128)
#define OFF_RED (OFF_ADJ + 256)
#define SMEM_WORDS (OFF_RED + 4*132)
#define SMEM_BYTES (SMEM_WORDS * 4)    // ~94 KB -> 2 CTAs/SM

// ---------------------------------------------------------------------------
// prep_node: 512 CTAs x 2 nodes, 256 threads (node = tid>>7, h = tid&127).
template<int C>
__global__ void prep_node4(const float* __restrict__ x,
                           const float* __restrict__ W1,
                           const float* __restrict__ b1,
                           float* __restrict__ A,
                           float* __restrict__ Bout)
{
    __shared__ float sx[2 * C];
    const int ni0 = blockIdx.x * 2;
    const int tid = threadIdx.x;
    const int h   = tid & 127;
    const int r   = tid >> 7;
    if (tid < 2 * C) sx[tid] = x[(size_t)ni0 * C + tid];
    __syncthreads();
    const float* xr = sx + r * C;
    float accA = 0.f, accB = 0.f;
#pragma unroll 8
    for (int c = 0; c < C; c++) {
        float wa = W1[c * 128 + h];
        float wb = W1[(C + c) * 128 + h];
        float xa = xr[c];
        accA += xa * (wa - wb);
        accB += xa * wb;
    }
    A   [(size_t)(ni0 + r) * 128 + h] = accA + b1[h];
    Bout[(size_t)(ni0 + r) * 128 + h] = accB;
}

// ---------------------------------------------------------------------------
// Fused edgeconv, bf16 mma + ldmatrix fragment loads. One CTA per (b,i),
// 256 threads = 8 warps (4 M-groups x 2 N-groups), 2 chunks of 128 j-rows.
__global__ __launch_bounds__(256, 2)
void fused_ec_bf16(const int*   __restrict__ adj,
                   const float* __restrict__ e,       // (B,V,V,32)
                   const float* __restrict__ A,
                   const float* __restrict__ Bnode,
                   const float* __restrict__ W1e,     // (32,128)
                   const float* __restrict__ W2,      // (128,128)
                   const float* __restrict__ b2,
                   float* __restrict__ xout)
{
    extern __shared__ float smem[];
    uint32_t* s32 = (uint32_t*)smem;
    const uint32_t sbase = (uint32_t)__cvta_generic_to_shared(smem);
    const int tid  = threadIdx.x;
    const int lane = tid & 31;
    const int wid  = tid >> 5;
    const int gid  = lane >> 2;      // 0..7
    const int tig  = lane & 3;       // 0..3
    const int WM   = wid & 3;        // rows WM*32 .. +31
    const int WN   = wid >> 2;       // cols WN*64 .. +63
    const int m0   = WM * 32;
    const int n0   = WN * 64;
    const int bi   = blockIdx.x;     // b*256 + i
    const int b    = bi >> 8;

    // ldmatrix per-lane address components
    const int lt = lane >> 3, lr = lane & 7;
    const int rA = ((lt & 1) << 3) + lr;   // A: row-group = lt&1, k-group = lt>>1
    const int wA = (lt >> 1) << 2;
    const int rB = ((lt >> 1) << 3) + lr;  // B: row-group = lt>>1, k-group = lt&1
    const int wB = (lt & 1) << 2;
    // byte bases (ks advances by 8 words = 32 B)
    const uint32_t aE0 = sbase + (uint32_t)(OFF_E   + (m0      + rA) * 20 + wA) * 4;
    const uint32_t aE1 = sbase + (uint32_t)(OFF_E   + (m0 + 16 + rA) * 20 + wA) * 4;
    const uint32_t aH0 = sbase + (uint32_t)(OFF_H1  + (m0      + rA) * 68 + wA) * 4;
    const uint32_t aH1 = sbase + (uint32_t)(OFF_H1  + (m0 + 16 + rA) * 68 + wA) * 4;
    const uint32_t bW1 = sbase + (uint32_t)(OFF_W1E + (n0 + rB) * 20 + wB) * 4;
    const uint32_t bW2 = sbase + (uint32_t)(OFF_W2T + (n0 + rB) * 68 + wB) * 4;

    // ---- stage W1e^T (n-major, k-paired, stride 20) ----
    {
        int n    = tid & 127;
        int half = tid >> 7;             // kw 0..7 or 8..15
#pragma unroll
        for (int kk = 0; kk < 8; kk++) {
            int kw = half * 8 + kk;
            s32[OFF_W1E + n * 20 + kw] =
                pack_bf2(W1e[(2*kw) * 128 + n], W1e[(2*kw + 1) * 128 + n]);
        }
    }
    // ---- stage W2^T (n-major, k-paired, stride 68) ----
    {
        int n    = tid & 127;
        int half = tid >> 7;             // kw 0..31 or 32..63
#pragma unroll 8
        for (int kk = 0; kk < 32; kk++) {
            int kw = half * 32 + kk;
            s32[OFF_W2T + n * 68 + kw] =
                pack_bf2(W2[(2*kw) * 128 + n], W2[(2*kw + 1) * 128 + n]);
        }
    }
    if (tid < 128) {
        smem[OFF_A  + tid] = A[(size_t)bi * 128 + tid];
        smem[OFF_B2 + tid] = b2[tid];
    }
    ((int*)(smem + OFF_ADJ))[tid] = adj[(size_t)bi * 256 + tid];

    float pmax = 0.0f;

    for (int chunk = 0; chunk < 2; chunk++) {
        const int j0 = chunk << 7;
        __syncthreads();   // staging / prior-chunk reuse

        // ---- stage E chunk: 128 rows x 16 kw (stride 20) ----
        {
            int row  = tid >> 1;
            int half = tid & 1;
            const float4* src = (const float4*)(e + ((size_t)bi * 256 + j0 + row) * 32 + half * 16);
            float4 v0 = src[0], v1 = src[1], v2 = src[2], v3 = src[3];
            uint32_t* d = s32 + OFF_E + row * 20 + half * 8;
            d[0] = pack_bf2(v0.x, v0.y); d[1] = pack_bf2(v0.z, v0.w);
            d[2] = pack_bf2(v1.x, v1.y); d[3] = pack_bf2(v1.z, v1.w);
            d[4] = pack_bf2(v2.x, v2.y); d[5] = pack_bf2(v2.z, v2.w);
            d[6] = pack_bf2(v3.x, v3.y); d[7] = pack_bf2(v3.z, v3.w);
        }
        __syncthreads();

        float acc[2][8][4];
#pragma unroll
        for (int mt = 0; mt < 2; mt++)
#pragma unroll
            for (int nt = 0; nt < 8; nt++)
#pragma unroll
                for (int q = 0; q < 4; q++) acc[mt][nt][q] = 0.f;

        // ---- GEMM1: D1 = E @ W1e  (K=32 -> 2 bf16 k-steps) ----
#pragma unroll
        for (int ks = 0; ks < 2; ks++) {
            uint32_t af[2][4];
            ldsm_x4(af[0], aE0 + ks * 32);
            ldsm_x4(af[1], aE1 + ks * 32);
#pragma unroll
            for (int np = 0; np < 4; np++) {
                uint32_t bf[4];
                ldsm_x4(bf, bW1 + (uint32_t)np * (16 * 20 * 4) + ks * 32);
                mma_bf16(acc[0][np*2],     af[0], bf);
                mma_bf16(acc[1][np*2],     af[1], bf);
                mma_bf16(acc[0][np*2 + 1], af[0], bf + 2);
                mma_bf16(acc[1][np*2 + 1], af[1], bf + 2);
            }
        }

        // ---- epilogue 1: H1 = relu(D1 + A_i[n] + Bnode[j,n]) -> bf16x2 ----
        {
            const float* sA_ = smem + OFF_A;
#pragma unroll
            for (int mt = 0; mt < 2; mt++) {
                const int r_lo = m0 + mt*16 + gid;
                const int r_hi = r_lo + 8;
                const float2* blo = (const float2*)(Bnode + ((size_t)(b*256 + j0 + r_lo)) * 128);
                const float2* bhi = (const float2*)(Bnode + ((size_t)(b*256 + j0 + r_hi)) * 128);
#pragma unroll
                for (int nt = 0; nt < 8; nt++) {
                    const int ncol = n0 + nt*8 + 2*tig;      // even
                    float2 bl = blo[ncol >> 1];
                    float2 bh = bhi[ncol >> 1];
                    float a0v = sA_[ncol], a1v = sA_[ncol + 1];
                    float h00 = fmaxf(acc[mt][nt][0] + a0v + bl.x, 0.f);
                    float h01 = fmaxf(acc[mt][nt][1] + a1v + bl.y, 0.f);
                    float h10 = fmaxf(acc[mt][nt][2] + a0v + bh.x, 0.f);
                    float h11 = fmaxf(acc[mt][nt][3] + a1v + bh.y, 0.f);
                    s32[OFF_H1 + r_lo * 68 + (ncol >> 1)] = pack_bf2(h00, h01);
                    s32[OFF_H1 + r_hi * 68 + (ncol >> 1)] = pack_bf2(h10, h11);
                }
            }
        }
        __syncthreads();

#pragma unroll
        for (int mt = 0; mt < 2; mt++)
#pragma unroll
            for (int nt = 0; nt < 8; nt++)
#pragma unroll
                for (int q = 0; q < 4; q++) acc[mt][nt][q] = 0.f;

        // ---- GEMM2: D2 = H1 @ W2  (K=128 -> 8 bf16 k-steps) ----
#pragma unroll 2
        for (int ks = 0; ks < 8; ks++) {
            uint32_t af[2][4];
            ldsm_x4(af[0], aH0 + ks * 32);
            ldsm_x4(af[1], aH1 + ks * 32);
#pragma unroll
            for (int np = 0; np < 4; np++) {
                uint32_t bf[4];
                ldsm_x4(bf, bW2 + (uint32_t)np * (16 * 68 * 4) + ks * 32);
                mma_bf16(acc[0][np*2],     af[0], bf);
                mma_bf16(acc[1][np*2],     af[1], bf);
                mma_bf16(acc[0][np*2 + 1], af[0], bf + 2);
                mma_bf16(acc[1][np*2 + 1], af[1], bf + 2);
            }
        }

        // ---- epilogue 2: bias+relu+mask, warp row-max -> red[WM][col] ----
        {
            const int* sAdj = (const int*)(smem + OFF_ADJ);
            const float* sb2_ = smem + OFF_B2;
            float* red = smem + OFF_RED;
            const bool kLo  = sAdj[j0 + m0 + gid]      > 0;
            const bool kHi  = sAdj[j0 + m0 + 8 + gid]  > 0;
            const bool kLo1 = sAdj[j0 + m0 + 16 + gid] > 0;
            const bool kHi1 = sAdj[j0 + m0 + 24 + gid] > 0;
#pragma unroll
            for (int nt = 0; nt < 8; nt++) {
                const int ncol = n0 + nt*8 + 2*tig;
                const float bb0 = sb2_[ncol], bb1 = sb2_[ncol + 1];
                float vA = 0.f, vB = 0.f;
                if (kLo)  { vA = fmaxf(vA, acc[0][nt][0] + bb0);
                            vB = fmaxf(vB, acc[0][nt][1] + bb1); }
                if (kHi)  { vA = fmaxf(vA, acc[0][nt][2] + bb0);
                            vB = fmaxf(vB, acc[0][nt][3] + bb1); }
                if (kLo1) { vA = fmaxf(vA, acc[1][nt][0] + bb0);
                            vB = fmaxf(vB, acc[1][nt][1] + bb1); }
                if (kHi1) { vA = fmaxf(vA, acc[1][nt][2] + bb0);
                            vB = fmaxf(vB, acc[1][nt][3] + bb1); }
#pragma unroll
                for (int msk = 4; msk <= 16; msk <<= 1) {
                    vA = fmaxf(vA, __shfl_xor_sync(0xffffffffu, vA, msk));
                    vB = fmaxf(vB, __shfl_xor_sync(0xffffffffu, vB, msk));
                }
                if (gid == 0) {
                    red[WM * 132 + ncol]     = vA;
                    red[WM * 132 + ncol + 1] = vB;
                }
            }
        }
        __syncthreads();
        if (tid < 128) {
            float v = fmaxf(fmaxf(smem[OFF_RED + tid],          smem[OFF_RED + 132 + tid]),
                            fmaxf(smem[OFF_RED + 2*132 + tid],  smem[OFF_RED + 3*132 + tid]));
            pmax = fmaxf(pmax, v);
        }
    }

    if (tid < 128) xout[(size_t)bi * 128 + tid] = pmax;
}

// ---------------------------------------------------------------------------
// pair prep: 512 CTAs x 2 rows, 512 threads (node = tid>>8, h = tid&255).
__global__ void pair_prep4(const float* __restrict__ x,     // (B*V,128)
                           const float* __restrict__ W3,    // (256,256)
                           float* __restrict__ P,
                           float* __restrict__ Q)
{
    __shared__ float sx[2 * 128];
    const int ni0 = blockIdx.x * 2;
    const int tid = threadIdx.x;
    const int h   = tid & 255;
    const int r   = tid >> 8;
    if (tid < 256) sx[tid] = x[(size_t)ni0 * 128 + tid];
    __syncthreads();
    const float* xr = sx + r * 128;
    float accP = 0.f, accQ = 0.f;
#pragma unroll 8
    for (int c = 0; c < 128; c++) {
        float xa = xr[c];
        accP += xa * W3[c * 256 + h];
        accQ += xa * W3[(128 + c) * 256 + h];
    }
    P[(size_t)(ni0 + r) * 256 + h] = accP;
    Q[(size_t)(ni0 + r) * 256 + h] = accQ;
}

// ---------------------------------------------------------------------------
// pair final: 256 CTAs; each handles (b, 4 i-rows) x all 256 j.
__global__ void pair_final3(const float* __restrict__ P,
                            const float* __restrict__ Q,
                            const float* __restrict__ b3,
                            const float* __restrict__ oW,
                            const float* __restrict__ ob,
                            float* __restrict__ out)        // (B,V,V)
{
    __shared__ float sQ[4 * 256];
    __shared__ float sW[256];
    const int blk = blockIdx.x;
    const int b   = blk >> 6;
    const int i0  = (blk & 63) * 4;
    const int tid = threadIdx.x;     // 256
    const int w   = tid >> 5, lane = tid & 31;
    sW[tid] = oW[tid];
    {
        float bb = b3[tid];
#pragma unroll
        for (int r = 0; r < 4; r++)
            sQ[r * 256 + tid] = Q[(size_t)(b * 256 + i0 + r) * 256 + tid] + bb;
    }
    __syncthreads();
    const float outb = ob[0];

    for (int j = w; j < 256; j += 8) {
        const float* pr = P + (size_t)(b * 256 + j) * 256;
        float s0 = 0.f, s1 = 0.f, s2 = 0.f, s3 = 0.f;
#pragma unroll
        for (int q = 0; q < 8; q++) {
            int hh = q * 32 + lane;
            float pv = pr[hh];
            float wv = sW[hh];
            s0 += fmaxf(pv + sQ[          hh], 0.f) * wv;
            s1 += fmaxf(pv + sQ[256     + hh], 0.f) * wv;
            s2 += fmaxf(pv + sQ[2 * 256 + hh], 0.f) * wv;
            s3 += fmaxf(pv + sQ[3 * 256 + hh], 0.f) * wv;
        }
#pragma unroll
        for (int off = 16; off > 0; off >>= 1) {
            s0 += __shfl_xor_sync(0xffffffffu, s0, off);
            s1 += __shfl_xor_sync(0xffffffffu, s1, off);
            s2 += __shfl_xor_sync(0xffffffffu, s2, off);
            s3 += __shfl_xor_sync(0xffffffffu, s3, off);
        }
        if (lane == 0) {
            out[(size_t)(b * 256 + i0 + 0) * 256 + j] = 1.0f / (1.0f + expf(-(s0 + outb)));
            out[(size_t)(b * 256 + i0 + 1) * 256 + j] = 1.0f / (1.0f + expf(-(s1 + outb)));
            out[(size_t)(b * 256 + i0 + 2) * 256 + j] = 1.0f / (1.0f + expf(-(s2 + outb)));
            out[(size_t)(b * 256 + i0 + 3) * 256 + j] = 1.0f / (1.0f + expf(-(s3 + outb)));
        }
    }
}

// ---------------------------------------------------------------------------
extern "C" void kernel_launch(void* const* d_in, const int* in_sizes, int n_in,
                              void* d_out, int out_size)
{
    const int*   adj   = (const int*)  d_in[0];
    const float* x0    = (const float*)d_in[1];
    const float* e     = (const float*)d_in[2];
    const float* ec1W1 = (const float*)d_in[3];
    const float* ec1b1 = (const float*)d_in[4];
    const float* ec1W2 = (const float*)d_in[5];
    const float* ec1b2 = (const float*)d_in[6];
    const float* ec2W1 = (const float*)d_in[7];
    const float* ec2b1 = (const float*)d_in[8];
    const float* ec2W2 = (const float*)d_in[9];
    const float* ec2b2 = (const float*)d_in[10];
    const float* h3W   = (const float*)d_in[11];
    const float* h3b   = (const float*)d_in[12];
    const float* oW    = (const float*)d_in[13];
    const float* ob    = (const float*)d_in[14];
    float* out = (float*)d_out;

    float *gA, *gB, *gx1, *gx2, *gP, *gQ;
    cudaGetSymbolAddress((void**)&gA,  g_A);
    cudaGetSymbolAddress((void**)&gB,  g_Bv);
    cudaGetSymbolAddress((void**)&gx1, g_x1);
    cudaGetSymbolAddress((void**)&gx2, g_x2);
    cudaGetSymbolAddress((void**)&gP,  g_P);
    cudaGetSymbolAddress((void**)&gQ,  g_Q);

    const int nBI = BN * VN;  // 1024
    cudaFuncSetAttribute(fused_ec_bf16,
                         cudaFuncAttributeMaxDynamicSharedMemorySize, SMEM_BYTES);

    // EdgeConvE #1
    prep_node4<C1N><<<512, 256>>>(x0, ec1W1, ec1b1, gA, gB);
    fused_ec_bf16<<<nBI, 256, SMEM_BYTES>>>(adj, e, gA, gB,
                                            ec1W1 + 2 * C1N * H0N, ec1W2, ec1b2, gx1);
    // EdgeConvE #2
    prep_node4<H0N><<<512, 256>>>(gx1, ec2W1, ec2b1, gA, gB);
    fused_ec_bf16<<<nBI, 256, SMEM_BYTES>>>(adj, e, gA, gB,
                                            ec2W1 + 2 * H0N * H0N, ec2W2, ec2b2, gx2);
    // pair scoring
    pair_prep4 <<<512, 512>>>(gx2, h3W, gP, gQ);
    pair_final3<<<256, 256>>>(gP, gQ, h3b, oW, ob, out);
}